// round 12
// baseline (speedup 1.0000x reference)
#include <cuda_runtime.h>

#define D      512
#define W      5
#define TPB    128
#define MAX_TIME_ROWS 512

// Precomputed fp32 sin/cos of the time table (row-major [rows][D]). L2-resident (1.5MB).
__device__ float g_sin[MAX_TIME_ROWS * D];
__device__ float g_cos[MAX_TIME_ROWS * D];
// Backward-step rotation: (ds,dc) = sincos(tt[row0] - tt[row1]) per dim (= -0.01*inc).
__device__ float g_dsin[D];
__device__ float g_dcos[D];

__global__ void trig_kernel(const float* __restrict__ tt, int n) {
    int i = blockIdx.x * blockDim.x + threadIdx.x;
    if (i < n) {
        float s, c;
        sincosf(tt[i], &s, &c);
        g_sin[i] = s;
        g_cos[i] = c;
    }
}

__global__ void delta_kernel(const float* __restrict__ tt) {
    int i = blockIdx.x * blockDim.x + threadIdx.x;
    if (i < D) {
        float s, c;
        sincosf(tt[i] - tt[D + i], &s, &c);   // angle(row i-1) - angle(row i)
        g_dsin[i] = s;
        g_dcos[i] = c;
    }
}

__global__ __launch_bounds__(TPB, 6) void contxe_kernel(
    const int*   __restrict__ h_i,
    const int*   __restrict__ t_i,
    const int*   __restrict__ r_i,
    const int*   __restrict__ d_i,
    const float* __restrict__ eEr,
    const float* __restrict__ eEi,
    const float* __restrict__ eRr,
    const float* __restrict__ eRi,
    float*       __restrict__ out,
    int n_day)
{
    const int b    = blockIdx.x;
    const int tid  = threadIdx.x;
    const int lane = tid & 31;
    const int warp = tid >> 5;

    __shared__ float acc_s[TPB * 20];   // 10 KB
    __shared__ float sums[20];
    __shared__ float sh_w[20];
    __shared__ float partial[4];

    const int h = h_i[b];
    const int t = t_i[b];
    const int r = r_i[b];
    const int d = d_i[b];

    // ---- Embedding gathers FIRST (DRAM latency — in flight early) ----
    const float4 hr4 = ((const float4*)(eEr + (size_t)h * D))[tid];
    const float4 hi4 = ((const float4*)(eEi + (size_t)h * D))[tid];
    const float4 tr4 = ((const float4*)(eEr + (size_t)t * D))[tid];
    const float4 ti4 = ((const float4*)(eEi + (size_t)t * D))[tid];
    const float4 rr4 = ((const float4*)(eRr + (size_t)r * D))[tid];
    const float4 ri4 = ((const float4*)(eRi + (size_t)r * D))[tid];

    // ---- Trig seeds: row d, pad row (n_day), backward delta (all L2 hits) ----
    const float4* sT = (const float4*)g_sin;
    const float4* cT = (const float4*)g_cos;
    float4 s4  = sT[d * (D / 4) + tid];
    float4 c4  = cT[d * (D / 4) + tid];
    const float4 ps4 = sT[n_day * (D / 4) + tid];
    const float4 pc4 = cT[n_day * (D / 4) + tid];
    const float4 ds4 = ((const float4*)g_dsin)[tid];
    const float4 dc4 = ((const float4*)g_dcos)[tid];

    const float* hrp = (const float*)&hr4;
    const float* hip = (const float*)&hi4;
    const float* trp = (const float*)&tr4;
    const float* tip = (const float*)&ti4;
    const float* rrp = (const float*)&rr4;
    const float* rip = (const float*)&ri4;
    const float* psp = (const float*)&ps4;
    const float* pcp = (const float*)&pc4;
    const float* dsp = (const float*)&ds4;
    const float* dcp = (const float*)&dc4;

    // ---- Pass 1: 20 attention-score partial dots; trig by backward rotation ----
    float acc[20];
    #pragma unroll
    for (int j = 0; j < 20; j++) acc[j] = 0.0f;

    {
        float* sp = (float*)&s4;
        float* cp = (float*)&c4;
        #pragma unroll
        for (int w = W - 1; w >= 0; w--) {          // row = d - (W-1-w)
            const bool pad = (W - 1 - w) > d;       // block-uniform
            #pragma unroll
            for (int k = 0; k < 4; k++) {
                const float su = pad ? psp[k] : sp[k];
                const float cu = pad ? pcp[k] : cp[k];
                const float hre = fmaf(hrp[k], cu, -hip[k] * su);
                const float him = fmaf(hrp[k], su,  hip[k] * cu);
                const float tre = fmaf(trp[k], cu, -tip[k] * su);
                const float tim = fmaf(trp[k], su,  tip[k] * cu);
                acc[0 * W + w] = fmaf(rrp[k], hre, acc[0 * W + w]);
                acc[1 * W + w] = fmaf(rip[k], him, acc[1 * W + w]);
                acc[2 * W + w] = fmaf(rrp[k], tre, acc[2 * W + w]);
                acc[3 * W + w] = fmaf(rip[k], tim, acc[3 * W + w]);
            }
            if (w > 0) {                            // rotate to row-1
                #pragma unroll
                for (int k = 0; k < 4; k++) {
                    const float sn = fmaf(sp[k], dcp[k],  cp[k] * dsp[k]);
                    cp[k]          = fmaf(cp[k], dcp[k], -sp[k] * dsp[k]);
                    sp[k] = sn;
                }
            }
        }
    }

    // ---- Cross-thread reduction: STS.128 dump + conflict-free column sums ----
    {
        float4* rowp = (float4*)(acc_s + tid * 20);
        #pragma unroll
        for (int j = 0; j < 5; j++)
            rowp[j] = make_float4(acc[4 * j], acc[4 * j + 1], acc[4 * j + 2], acc[4 * j + 3]);
    }
    __syncthreads();

    if (tid < 20) {
        float v0 = 0.f, v1 = 0.f, v2 = 0.f, v3 = 0.f;
        #pragma unroll
        for (int i = 0; i < TPB; i += 4) {
            v0 += acc_s[(i + 0) * 20 + tid];
            v1 += acc_s[(i + 1) * 20 + tid];
            v2 += acc_s[(i + 2) * 20 + tid];
            v3 += acc_s[(i + 3) * 20 + tid];
        }
        sums[tid] = (v0 + v1) + (v2 + v3);
    }
    __syncthreads();

    // ---- 4 threads each do one 5-way softmax ----
    if (tid < 4) {
        float sc[W];
        float m = -1e30f;
        #pragma unroll
        for (int w = 0; w < W; w++) {
            sc[w] = sums[tid * W + w];
            m = fmaxf(m, sc[w]);
        }
        float sum = 0.0f;
        #pragma unroll
        for (int w = 0; w < W; w++) {
            sc[w] = expf(sc[w] - m);
            sum += sc[w];
        }
        float inv = 1.0f / sum;
        #pragma unroll
        for (int w = 0; w < W; w++) sh_w[tid * W + w] = sc[w] * inv;
    }
    __syncthreads();

    // ---- Pass 2: reload row-d trig (L1 hit), weighted sums by rotation ----
    s4 = sT[d * (D / 4) + tid];
    c4 = cT[d * (D / 4) + tid];

    float yre[4] = {0, 0, 0, 0};
    float yim[4] = {0, 0, 0, 0};
    float zre[4] = {0, 0, 0, 0};
    float zim[4] = {0, 0, 0, 0};

    {
        float* sp = (float*)&s4;
        float* cp = (float*)&c4;
        #pragma unroll
        for (int w = W - 1; w >= 0; w--) {
            const float wa_r = sh_w[0 * W + w];   // LDS broadcasts
            const float wa_i = sh_w[1 * W + w];
            const float wb_r = sh_w[2 * W + w];
            const float wb_i = sh_w[3 * W + w];
            const bool pad = (W - 1 - w) > d;
            #pragma unroll
            for (int k = 0; k < 4; k++) {
                const float su = pad ? psp[k] : sp[k];
                const float cu = pad ? pcp[k] : cp[k];
                const float hre = fmaf(hrp[k], cu, -hip[k] * su);
                const float him = fmaf(hrp[k], su,  hip[k] * cu);
                const float tre = fmaf(trp[k], cu, -tip[k] * su);
                const float tim = fmaf(trp[k], su,  tip[k] * cu);
                yre[k] = fmaf(wa_r, hre, yre[k]);
                yim[k] = fmaf(wa_i, him, yim[k]);
                zre[k] = fmaf(wb_r, tre, zre[k]);
                zim[k] = fmaf(wb_i, tim, zim[k]);
            }
            if (w > 0) {
                #pragma unroll
                for (int k = 0; k < 4; k++) {
                    const float sn = fmaf(sp[k], dcp[k],  cp[k] * dsp[k]);
                    cp[k]          = fmaf(cp[k], dcp[k], -sp[k] * dsp[k]);
                    sp[k] = sn;
                }
            }
        }
    }

    float local = 0.0f;
    #pragma unroll
    for (int k = 0; k < 4; k++) {
        local += fabsf(yre[k] + rrp[k] - zre[k]);
        local += fabsf(yim[k] + rip[k] + zim[k]);
    }

    local += __shfl_xor_sync(0xffffffffu, local, 16);
    local += __shfl_xor_sync(0xffffffffu, local, 8);
    local += __shfl_xor_sync(0xffffffffu, local, 4);
    local += __shfl_xor_sync(0xffffffffu, local, 2);
    local += __shfl_xor_sync(0xffffffffu, local, 1);
    if (lane == 0) partial[warp] = local;
    __syncthreads();

    if (tid == 0) {
        out[b] = (partial[0] + partial[1]) + (partial[2] + partial[3]);
    }
}

extern "C" void kernel_launch(void* const* d_in, const int* in_sizes, int n_in,
                              void* d_out, int out_size) {
    const int*   h_i = (const int*)  d_in[0];
    const int*   t_i = (const int*)  d_in[1];
    const int*   r_i = (const int*)  d_in[2];
    const int*   d_i = (const int*)  d_in[3];
    const float* eEr = (const float*)d_in[4];
    const float* eEi = (const float*)d_in[5];
    const float* eRr = (const float*)d_in[6];
    const float* eRi = (const float*)d_in[7];
    const float* tt  = (const float*)d_in[8];

    const int B          = in_sizes[0];
    const int time_elems = in_sizes[8];
    const int time_rows  = time_elems / D;
    const int n_day      = time_rows - 2;

    trig_kernel<<<(time_elems + 255) / 256, 256>>>(tt, time_elems);
    delta_kernel<<<(D + 255) / 256, 256>>>(tt);
    contxe_kernel<<<B, TPB>>>(h_i, t_i, r_i, d_i, eEr, eEi, eRr, eRi,
                              (float*)d_out, n_day);
}